// round 14
// baseline (speedup 1.0000x reference)
#include <cuda_runtime.h>
#include <math.h>

// BPR loss:
//   per_sample[b] = -( sum_{i<L, j<L, k<S} log_sigmoid( out[b,i,lab[b,j]] - out[b,i,neg[b,j,k]] ) ) / (L^2 * S)
//   result = sum_b per_sample[b]     (shape [1], float32)
//
// Inputs (harness delivers int64 as int32):
//   d_in[0] output  : float32 [B, T, V]
//   d_in[1] labels  : int32   [B, T]
//   d_in[2] x_lens  : int32   [B]
//   d_in[3] uids    : int32   [B, 1]  (unused)
//   d_in[4] neg_ids : int32   [B, T, S]
//
// R14 = R13 main kernel (128 thr, __ldcg gathers; at the random-gather DRAM
// floor ~68% / 5.4TB/s) + single-kernel finalization WITHOUT __threadfence:
// all cross-block state stays in the atomic (L2) domain. Ticket uses
// atom.acq_rel.gpu (release orders this block's g_acc add; acquire
// synchronizes the last block with all earlier releases). Last block drains
// g_acc via atomicExch (atomic read+reset, L2-coherent by construction),
// publishes result[0], and resets the ticket — state identical every launch,
// so graph replay is deterministic. No CCTL.IVALL anywhere (R7/R8: ~8us).

__device__ float        g_acc  = 0.0f;
__device__ unsigned int g_done = 0u;

__device__ __forceinline__ float warp_reduce_add(float v) {
#pragma unroll
    for (int off = 16; off > 0; off >>= 1)
        v += __shfl_down_sync(0xFFFFFFFFu, v, off);
    return v;
}

__device__ __forceinline__ float log_sigmoid_fast(float d) {
    // min(d,0) - log(1 + exp(-|d|)); exp arg <= 0 so log arg in (1,2]
    return fminf(d, 0.0f) - __logf(1.0f + __expf(-fabsf(d)));
}

__device__ __forceinline__ unsigned int ticket_acq_rel(unsigned int* addr) {
    unsigned int old;
    asm volatile("atom.acq_rel.gpu.global.add.u32 %0, [%1], 1;"
                 : "=r"(old) : "l"(addr) : "memory");
    return old;
}

__global__ void __launch_bounds__(128)
bpr_loss_kernel(const float* __restrict__ out3d,   // [B,T,V]
                const int* __restrict__ labels,    // [B,T]
                const int* __restrict__ x_lens,    // [B]
                const int* __restrict__ neg_ids,   // [B,T,S]
                float* __restrict__ result,        // [1]
                int T, int V, int S)
{
    const int b = blockIdx.y;
    const int i = blockIdx.x;
    const int L = x_lens[b];

    float acc = 0.0f;
    if (i < L) {
        const float* __restrict__ row = out3d + ((size_t)b * T + i) * (size_t)V;
        const int* __restrict__ lab = labels + (size_t)b * T;
        const int* __restrict__ neg = neg_ids + (size_t)b * T * S;

        if (S == 1) {
            for (int j = threadIdx.x; j < L; j += blockDim.x) {
                const int c_pos = __ldg(lab + j);
                const int c_neg = __ldg(neg + j);
                const float pv = __ldcg(row + c_pos);
                const float nv = __ldcg(row + c_neg);
                acc += log_sigmoid_fast(pv - nv);
            }
        } else {
            for (int j = threadIdx.x; j < L; j += blockDim.x) {
                const float pv = __ldcg(row + __ldg(lab + j));
                for (int k = 0; k < S; ++k)
                    acc += log_sigmoid_fast(pv - __ldcg(row + __ldg(neg + (size_t)j * S + k)));
            }
        }
    }

    // block reduction (4 warps); every block reaches the ticket
    __shared__ float warp_sums[4];
    const int lane = threadIdx.x & 31;
    const int wid  = threadIdx.x >> 5;
    acc = warp_reduce_add(acc);
    if (lane == 0) warp_sums[wid] = acc;
    __syncthreads();

    if (threadIdx.x == 0) {
        if (i < L) {
            const float v = warp_sums[0] + warp_sums[1] + warp_sums[2] + warp_sums[3];
            const float Lf = (float)L;
            atomicAdd(&g_acc, v * (-1.0f / (Lf * Lf * (float)S)));
        }
        const unsigned int total  = gridDim.x * gridDim.y;
        const unsigned int ticket = ticket_acq_rel(&g_done);
        if (ticket == total - 1u) {
            // last block: atomically drain + reset accumulator, publish, reset ticket
            const float sum = atomicExch(&g_acc, 0.0f);
            result[0] = sum;
            g_done = 0u;
        }
    }
}

extern "C" void kernel_launch(void* const* d_in, const int* in_sizes, int n_in,
                              void* d_out, int out_size)
{
    const float* out3d   = (const float*)d_in[0];
    const int*   labels  = (const int*)d_in[1];
    const int*   x_lens  = (const int*)d_in[2];
    const int*   neg_ids = (const int*)d_in[4];
    float* result = (float*)d_out;

    const int B = in_sizes[2];                 // x_lens: B
    const int T = in_sizes[1] / B;             // labels: B*T
    const int V = in_sizes[0] / (B * T);       // output: B*T*V
    const int S = in_sizes[4] / (B * T);       // neg_ids: B*T*S

    dim3 grid(T, B);
    bpr_loss_kernel<<<grid, 128>>>(out3d, labels, x_lens, neg_ids, result, T, V, S);
}

// round 15
// speedup vs baseline: 1.0425x; 1.0425x over previous
#include <cuda_runtime.h>
#include <math.h>

// BPR loss:
//   per_sample[b] = -( sum_{i<L, j<L, k<S} log_sigmoid( out[b,i,lab[b,j]] - out[b,i,neg[b,j,k]] ) ) / (L^2 * S)
//   result = sum_b per_sample[b]     (shape [1], float32)
//
// Inputs (harness delivers int64 as int32):
//   d_in[0] output  : float32 [B, T, V]
//   d_in[1] labels  : int32   [B, T]
//   d_in[2] x_lens  : int32   [B]
//   d_in[3] uids    : int32   [B, 1]  (unused)
//   d_in[4] neg_ids : int32   [B, T, S]
//
// FINAL (R13 config) — converged after 13 controlled experiments:
//  * block-per-row, 128 thr, grid (T,B): oversubscribed grid self-load-
//    balances (persistent variants lose: R10 barrier drain, R11 tail/MLP).
//  * __ldcg row gathers (L2-only; neutral vs __ldg, avoids L1 pollution).
//  * separate 1-block zero kernel. This overhead (~0.5-1us) is IRREDUCIBLE:
//    - memset graph node costs more (+1.9us, R9);
//    - fused finalization needs gpu-scope ordering (fence OR acq_rel atomic),
//      and BOTH trigger per-block L1D invalidation (CCTL.IVALL) on sm_103a:
//      +8us at this grid size (reproduced 3x: R7, R8, R14).
//  * main kernel sits at the random-gather DRAM floor: ~5.4TB/s, ~68% DRAM
//    active, ~177MB effective traffic for ~7MB useful data (64B+ granularity
//    on random 4B gathers over V=20000 columns). MLP batching (R3), sorted
//    sweeps (R4/R5), cache policy (R6), and launch geometry (R13) are all
//    floor-invariant.

__global__ void zero_out_kernel(float* __restrict__ out) {
    if (threadIdx.x == 0) out[0] = 0.0f;
}

__device__ __forceinline__ float warp_reduce_add(float v) {
#pragma unroll
    for (int off = 16; off > 0; off >>= 1)
        v += __shfl_down_sync(0xFFFFFFFFu, v, off);
    return v;
}

__device__ __forceinline__ float log_sigmoid_fast(float d) {
    // min(d,0) - log(1 + exp(-|d|)); exp arg <= 0 so log arg in (1,2]
    return fminf(d, 0.0f) - __logf(1.0f + __expf(-fabsf(d)));
}

__global__ void __launch_bounds__(128)
bpr_loss_kernel(const float* __restrict__ out3d,   // [B,T,V]
                const int* __restrict__ labels,    // [B,T]
                const int* __restrict__ x_lens,    // [B]
                const int* __restrict__ neg_ids,   // [B,T,S]
                float* __restrict__ result,        // [1]
                int T, int V, int S)
{
    const int b = blockIdx.y;
    const int i = blockIdx.x;
    const int L = x_lens[b];
    if (i >= L) return;

    const float* __restrict__ row = out3d + ((size_t)b * T + i) * (size_t)V;
    const int* __restrict__ lab = labels + (size_t)b * T;
    const int* __restrict__ neg = neg_ids + (size_t)b * T * S;

    float acc = 0.0f;
    if (S == 1) {
        for (int j = threadIdx.x; j < L; j += blockDim.x) {
            const int c_pos = __ldg(lab + j);
            const int c_neg = __ldg(neg + j);
            const float pv = __ldcg(row + c_pos);
            const float nv = __ldcg(row + c_neg);
            acc += log_sigmoid_fast(pv - nv);
        }
    } else {
        for (int j = threadIdx.x; j < L; j += blockDim.x) {
            const float pv = __ldcg(row + __ldg(lab + j));
            for (int k = 0; k < S; ++k)
                acc += log_sigmoid_fast(pv - __ldcg(row + __ldg(neg + (size_t)j * S + k)));
        }
    }

    // block reduction (4 warps)
    __shared__ float warp_sums[4];
    const int lane = threadIdx.x & 31;
    const int wid  = threadIdx.x >> 5;
    acc = warp_reduce_add(acc);
    if (lane == 0) warp_sums[wid] = acc;
    __syncthreads();
    if (wid == 0) {
        float v = (lane < 4) ? warp_sums[lane] : 0.0f;
        v = warp_reduce_add(v);
        if (lane == 0) {
            const float Lf = (float)L;
            atomicAdd(result, v * (-1.0f / (Lf * Lf * (float)S)));
        }
    }
}

extern "C" void kernel_launch(void* const* d_in, const int* in_sizes, int n_in,
                              void* d_out, int out_size)
{
    const float* out3d   = (const float*)d_in[0];
    const int*   labels  = (const int*)d_in[1];
    const int*   x_lens  = (const int*)d_in[2];
    const int*   neg_ids = (const int*)d_in[4];
    float* result = (float*)d_out;

    const int B = in_sizes[2];                 // x_lens: B
    const int T = in_sizes[1] / B;             // labels: B*T
    const int V = in_sizes[0] / (B * T);       // output: B*T*V
    const int S = in_sizes[4] / (B * T);       // neg_ids: B*T*S

    zero_out_kernel<<<1, 32>>>(result);

    dim3 grid(T, B);
    bpr_loss_kernel<<<grid, 128>>>(out3d, labels, x_lens, neg_ids, result, T, V, S);
}

// round 16
// speedup vs baseline: 1.0534x; 1.0105x over previous
#include <cuda_runtime.h>
#include <math.h>

// BPR loss:
//   per_sample[b] = -( sum_{i<L, j<L, k<S} log_sigmoid( out[b,i,lab[b,j]] - out[b,i,neg[b,j,k]] ) ) / (L^2 * S)
//   result = sum_b per_sample[b]     (shape [1], float32)
//
// Inputs (harness delivers int64 as int32):
//   d_in[0] output  : float32 [B, T, V]
//   d_in[1] labels  : int32   [B, T]
//   d_in[2] x_lens  : int32   [B]
//   d_in[3] uids    : int32   [B, 1]  (unused)
//   d_in[4] neg_ids : int32   [B, T, S]
//
// FINAL — converged after 14 controlled experiments (R2-R15):
//  * block-per-row, 128 thr, grid (T,B): oversubscribed grid self-load-
//    balances (persistent variants lose: R10 barrier drain, R11 tail/MLP).
//  * __ldcg row gathers (L2-only; neutral vs __ldg, avoids L1 pollution).
//  * separate 1-block zero kernel; this ~0.5-1us is irreducible:
//    memset node costs +1.9us (R9); fused finalization requires gpu-scope
//    ordering (fence OR acq_rel atomic) and either triggers per-block L1D
//    invalidation (CCTL.IVALL) on sm_103a: +8us (reproduced R7, R8, R14).
//  * main kernel sits at the random-gather DRAM floor: ~5.4-5.5TB/s, ~68%
//    DRAM active, ~177MB effective traffic for ~7MB useful data (>=64B
//    granularity on random 4B gathers over V=20000). MLP batching (R3),
//    sorted sweeps (R4/R5), cache policy (R6), and launch geometry (R13)
//    are all floor-invariant.

__global__ void zero_out_kernel(float* __restrict__ out) {
    if (threadIdx.x == 0) out[0] = 0.0f;
}

__device__ __forceinline__ float warp_reduce_add(float v) {
#pragma unroll
    for (int off = 16; off > 0; off >>= 1)
        v += __shfl_down_sync(0xFFFFFFFFu, v, off);
    return v;
}

__device__ __forceinline__ float log_sigmoid_fast(float d) {
    // min(d,0) - log(1 + exp(-|d|)); exp arg <= 0 so log arg in (1,2]
    return fminf(d, 0.0f) - __logf(1.0f + __expf(-fabsf(d)));
}

__global__ void __launch_bounds__(128)
bpr_loss_kernel(const float* __restrict__ out3d,   // [B,T,V]
                const int* __restrict__ labels,    // [B,T]
                const int* __restrict__ x_lens,    // [B]
                const int* __restrict__ neg_ids,   // [B,T,S]
                float* __restrict__ result,        // [1]
                int T, int V, int S)
{
    const int b = blockIdx.y;
    const int i = blockIdx.x;
    const int L = x_lens[b];
    if (i >= L) return;

    const float* __restrict__ row = out3d + ((size_t)b * T + i) * (size_t)V;
    const int* __restrict__ lab = labels + (size_t)b * T;
    const int* __restrict__ neg = neg_ids + (size_t)b * T * S;

    float acc = 0.0f;
    if (S == 1) {
        for (int j = threadIdx.x; j < L; j += blockDim.x) {
            const int c_pos = __ldg(lab + j);
            const int c_neg = __ldg(neg + j);
            const float pv = __ldcg(row + c_pos);
            const float nv = __ldcg(row + c_neg);
            acc += log_sigmoid_fast(pv - nv);
        }
    } else {
        for (int j = threadIdx.x; j < L; j += blockDim.x) {
            const float pv = __ldcg(row + __ldg(lab + j));
            for (int k = 0; k < S; ++k)
                acc += log_sigmoid_fast(pv - __ldcg(row + __ldg(neg + (size_t)j * S + k)));
        }
    }

    // block reduction (4 warps)
    __shared__ float warp_sums[4];
    const int lane = threadIdx.x & 31;
    const int wid  = threadIdx.x >> 5;
    acc = warp_reduce_add(acc);
    if (lane == 0) warp_sums[wid] = acc;
    __syncthreads();
    if (wid == 0) {
        float v = (lane < 4) ? warp_sums[lane] : 0.0f;
        v = warp_reduce_add(v);
        if (lane == 0) {
            const float Lf = (float)L;
            atomicAdd(result, v * (-1.0f / (Lf * Lf * (float)S)));
        }
    }
}

extern "C" void kernel_launch(void* const* d_in, const int* in_sizes, int n_in,
                              void* d_out, int out_size)
{
    const float* out3d   = (const float*)d_in[0];
    const int*   labels  = (const int*)d_in[1];
    const int*   x_lens  = (const int*)d_in[2];
    const int*   neg_ids = (const int*)d_in[4];
    float* result = (float*)d_out;

    const int B = in_sizes[2];                 // x_lens: B
    const int T = in_sizes[1] / B;             // labels: B*T
    const int V = in_sizes[0] / (B * T);       // output: B*T*V
    const int S = in_sizes[4] / (B * T);       // neg_ids: B*T*S

    zero_out_kernel<<<1, 32>>>(result);

    dim3 grid(T, B);
    bpr_loss_kernel<<<grid, 128>>>(out3d, labels, x_lens, neg_ids, result, T, V, S);
}